// round 7
// baseline (speedup 1.0000x reference)
#include <cuda_runtime.h>
#include <cuda_bf16.h>
#include <math.h>

// ---------------------------------------------------------------------------
// 2-layer GCN, N=1M, E=4M, 4 -> 16 -> 2, log_softmax.
// Dst-binned edges (2048 nodes/bucket): per-bucket SMEM accumulators replace
// all global REDs. Degree/dinv/xs fused into a binned pass; layer MLP and
// log_softmax fused into the scatter epilogues.
// ---------------------------------------------------------------------------

#define NMAX  1048576
#define NBITS 11
#define BSZ   2048                 // nodes per bucket
#define NBMAX 512
#define CAP   12288                // edges per bucket capacity (mean ~8184)

__device__ int2  g_bins[NBMAX * CAP];   // binned (src, dst)
__device__ int   g_cursor[NBMAX];
__device__ float g_dinv[NMAX];
__device__ float g_xs  [NMAX * 4];      // x * dinv
__device__ float g_h2  [NMAX * 2];      // (h @ W2) * dinv
__device__ int   g_ei64;

// --- dtype detection: int64 indices < 2^20 have all-zero high words --------
__global__ void k_detect(const unsigned* ei) {
    unsigned hi = ei[2 * threadIdx.x + 1];
    unsigned any = __ballot_sync(0xffffffffu, hi != 0u);
    if (threadIdx.x == 0) g_ei64 = (any == 0u) ? 1 : 0;
}

// --- bin edges by dst bucket; block-staged cursor atomics ------------------
#define BIN_T 256
#define EPT   16
#define EPB   (BIN_T * EPT)   // 4096 edges per block

__global__ void k_bin(const void* ei, int E, int NB) {
    __shared__ int s_cnt[NBMAX];
    __shared__ int s_base[NBMAX];
    int tid = threadIdx.x;
    for (int b = tid; b < NB; b += BIN_T) s_cnt[b] = 0;
    __syncthreads();

    int e0 = blockIdx.x * EPB + tid * EPT;
    int cnt_t = E - e0; if (cnt_t > EPT) cnt_t = EPT; if (cnt_t < 0) cnt_t = 0;

    int s[EPT], d[EPT], sl[EPT];
    if (cnt_t == EPT) {
        if (g_ei64) {
            const longlong2* ps = (const longlong2*)((const long long*)ei + e0);
            const longlong2* pd = (const longlong2*)((const long long*)ei + E + e0);
#pragma unroll
            for (int j = 0; j < EPT / 2; j++) {
                longlong2 a = __ldg(ps + j); longlong2 bb = __ldg(pd + j);
                s[2*j] = (int)a.x; s[2*j+1] = (int)a.y;
                d[2*j] = (int)bb.x; d[2*j+1] = (int)bb.y;
            }
        } else {
            const int4* ps = (const int4*)((const int*)ei + e0);
            const int4* pd = (const int4*)((const int*)ei + E + e0);
#pragma unroll
            for (int j = 0; j < EPT / 4; j++) {
                int4 a = __ldg(ps + j); int4 bb = __ldg(pd + j);
                s[4*j] = a.x; s[4*j+1] = a.y; s[4*j+2] = a.z; s[4*j+3] = a.w;
                d[4*j] = bb.x; d[4*j+1] = bb.y; d[4*j+2] = bb.z; d[4*j+3] = bb.w;
            }
        }
    } else {
        for (int j = 0; j < cnt_t; j++) {
            if (g_ei64) {
                const long long* p = (const long long*)ei;
                s[j] = (int)__ldg(p + e0 + j); d[j] = (int)__ldg(p + E + e0 + j);
            } else {
                const int* p = (const int*)ei;
                s[j] = __ldg(p + e0 + j); d[j] = __ldg(p + E + e0 + j);
            }
        }
    }
#pragma unroll
    for (int j = 0; j < EPT; j++)
        if (j < cnt_t) sl[j] = atomicAdd(&s_cnt[d[j] >> NBITS], 1);
    __syncthreads();
    for (int b = tid; b < NB; b += BIN_T) {
        int c = s_cnt[b];
        s_base[b] = c ? atomicAdd(&g_cursor[b], c) : 0;
    }
    __syncthreads();
#pragma unroll
    for (int j = 0; j < EPT; j++) {
        if (j >= cnt_t) break;
        int b = d[j] >> NBITS;
        int slot = s_base[b] + sl[j];
        if (slot < CAP) g_bins[b * CAP + slot] = make_int2(s[j], d[j]);
    }
}

// --- per-bucket: degree count in smem -> dinv, xs = x*dinv ----------------
__global__ void k_deg(const float* __restrict__ x, int N) {
    __shared__ int s_cnt[BSZ];
    int b = blockIdx.x, tid = threadIdx.x;
    int nb0 = b << NBITS;
    for (int i = tid; i < BSZ; i += blockDim.x) s_cnt[i] = 0;
    __syncthreads();
    int cnt = g_cursor[b]; if (cnt > CAP) cnt = CAP;
    const int2* bin = &g_bins[b * CAP];
    for (int e = tid; e < cnt; e += blockDim.x) {
        int2 sd = __ldg(bin + e);
        atomicAdd(&s_cnt[sd.y - nb0], 1);
    }
    __syncthreads();
    for (int i = tid; i < BSZ; i += blockDim.x) {
        int node = nb0 + i;
        if (node < N) {
            float di = rsqrtf((float)(s_cnt[i] + 1));   // +1 self loop
            g_dinv[node] = di;
            float4 xv = __ldg(&((const float4*)x)[node]);
            ((float4*)g_xs)[node] = make_float4(xv.x*di, xv.y*di, xv.z*di, xv.w*di);
        }
    }
}

// --- layer-1 scatter (smem acc, init=xs self-loop) + MLP epilogue ---------
__global__ void k_s1(const float* __restrict__ W1, const float* __restrict__ b1,
                     const float* __restrict__ W2, int N) {
    __shared__ float4 s_acc[BSZ];            // 32 KB
    __shared__ float sW1[64], sb1[16], sW2[32];
    int b = blockIdx.x, tid = threadIdx.x;
    int nb0 = b << NBITS;
    if (tid < 64)        sW1[tid]      = W1[tid];
    else if (tid < 80)   sb1[tid - 64] = b1[tid - 64];
    else if (tid < 112)  sW2[tid - 80] = W2[tid - 80];
    for (int i = tid; i < BSZ; i += blockDim.x) {
        int node = nb0 + i;
        s_acc[i] = (node < N) ? ((const float4*)g_xs)[node]
                              : make_float4(0.f, 0.f, 0.f, 0.f);
    }
    __syncthreads();
    int cnt = g_cursor[b]; if (cnt > CAP) cnt = CAP;
    const int2* bin = &g_bins[b * CAP];
    for (int e = tid; e < cnt; e += blockDim.x) {
        int2 sd = __ldg(bin + e);
        float4 v = __ldg(&((const float4*)g_xs)[sd.x]);
        float* a = (float*)&s_acc[sd.y - nb0];
        atomicAdd(a + 0, v.x); atomicAdd(a + 1, v.y);
        atomicAdd(a + 2, v.z); atomicAdd(a + 3, v.w);
    }
    __syncthreads();
    for (int i = tid; i < BSZ; i += blockDim.x) {
        int node = nb0 + i;
        if (node >= N) continue;
        float di = g_dinv[node];
        float4 av = s_acc[i];
        float o0 = 0.f, o1 = 0.f;
#pragma unroll
        for (int k = 0; k < 16; k++) {
            float h = di * (av.x * sW1[k]      + av.y * sW1[16 + k] +
                            av.z * sW1[32 + k] + av.w * sW1[48 + k]) + sb1[k];
            h = fmaxf(h, 0.f);
            o0 += h * sW2[2 * k];
            o1 += h * sW2[2 * k + 1];
        }
        ((float2*)g_h2)[node] = make_float2(o0 * di, o1 * di);
    }
}

// --- layer-2 scatter (smem acc, init=h2 self-loop) + log_softmax ----------
__global__ void k_s2(const float* __restrict__ b2, float* __restrict__ out, int N) {
    __shared__ float2 s_acc[BSZ];            // 16 KB
    int b = blockIdx.x, tid = threadIdx.x;
    int nb0 = b << NBITS;
    for (int i = tid; i < BSZ; i += blockDim.x) {
        int node = nb0 + i;
        s_acc[i] = (node < N) ? ((const float2*)g_h2)[node] : make_float2(0.f, 0.f);
    }
    __syncthreads();
    int cnt = g_cursor[b]; if (cnt > CAP) cnt = CAP;
    const int2* bin = &g_bins[b * CAP];
    for (int e = tid; e < cnt; e += blockDim.x) {
        int2 sd = __ldg(bin + e);
        float2 v = __ldg(&((const float2*)g_h2)[sd.x]);
        float* a = (float*)&s_acc[sd.y - nb0];
        atomicAdd(a + 0, v.x); atomicAdd(a + 1, v.y);
    }
    __syncthreads();
    float2 bb = __ldg((const float2*)b2);
    for (int i = tid; i < BSZ; i += blockDim.x) {
        int node = nb0 + i;
        if (node >= N) continue;
        float di = g_dinv[node];
        float2 a = s_acc[i];
        float o0 = di * a.x + bb.x;
        float o1 = di * a.y + bb.y;
        float m = fmaxf(o0, o1);
        float ls = m + __logf(__expf(o0 - m) + __expf(o1 - m));
        ((float2*)out)[node] = make_float2(o0 - ls, o1 - ls);
    }
}

extern "C" void kernel_launch(void* const* d_in, const int* in_sizes, int n_in,
                              void* d_out, int out_size) {
    const float* x  = (const float*)d_in[0];
    const void*  ei = d_in[1];
    int wi = 2;
    if (n_in >= 7 && in_sizes[2] < 16) wi = 3;  // skip num_nodes scalar
    const float* W1 = (const float*)d_in[wi];
    const float* b1 = (const float*)d_in[wi + 1];
    const float* W2 = (const float*)d_in[wi + 2];
    const float* b2 = (const float*)d_in[wi + 3];

    int N = in_sizes[0] / 4;
    int E = in_sizes[1] / 2;
    int NB = (N + BSZ - 1) >> NBITS;            // 489 for N=1e6
    if (NB > NBMAX) NB = NBMAX;

    void* curp = nullptr;
    cudaGetSymbolAddress(&curp, g_cursor);

    k_detect<<<1, 32>>>((const unsigned*)ei);
    cudaMemsetAsync(curp, 0, (size_t)NB * sizeof(int));
    k_bin<<<(E + EPB - 1) / EPB, BIN_T>>>(ei, E, NB);
    k_deg<<<NB, 512>>>(x, N);
    k_s1<<<NB, 512>>>(W1, b1, W2, N);
    k_s2<<<NB, 512>>>(b2, (float*)d_out, N);
}

// round 8
// speedup vs baseline: 1.3139x; 1.3139x over previous
#include <cuda_runtime.h>
#include <cuda_bf16.h>
#include <math.h>

// ---------------------------------------------------------------------------
// 2-layer GCN, N=1M, E=4M, 4 -> 16 -> 2, log_softmax.
// Edges binned by SRC bucket (2048 nodes), packed (local_src<<20)|dst.
// Scatters stage the bucket's source features in SMEM (gather -> LDS) and
// accumulate with global red.v4/v2 (L2-slice parallel; never smem atomics).
// ---------------------------------------------------------------------------

#define NMAX  1048576
#define NBITS 11
#define BSZ   2048
#define NBMAX 512
#define CAP   12288        // per-bucket capacity (mean ~8184 for E=4M)

__device__ unsigned g_bins[NBMAX * CAP];  // (local_src << 20) | dst
__device__ int      g_cursor[NBMAX];
__device__ int      g_deg [NMAX];
__device__ float    g_dinv[NMAX];
__device__ float    g_xs  [NMAX * 4];     // x * dinv
__device__ float    g_a1  [NMAX * 4];     // layer-1 acc, init = xs (self loop)
__device__ float    g_h2  [NMAX * 2];     // (h@W2)*dinv
__device__ float    g_a2  [NMAX * 2];     // layer-2 acc, init = h2 (self loop)
__device__ int      g_ei64;

#define RED4(idx, v) \
    asm volatile("red.global.add.v4.f32 [%0], {%1,%2,%3,%4};" \
                 :: "l"(&((float4*)g_a1)[idx]), "f"((v).x), "f"((v).y), "f"((v).z), "f"((v).w) : "memory")
#define RED2(idx, v) \
    asm volatile("red.global.add.v2.f32 [%0], {%1,%2};" \
                 :: "l"(&((float2*)g_a2)[idx]), "f"((v).x), "f"((v).y) : "memory")
#define REDI(p) \
    asm volatile("red.global.add.u32 [%0], %1;" :: "l"(p), "r"(1) : "memory")

// --- dtype detection: int64 indices < 2^20 have all-zero high words --------
__global__ void k_detect(const unsigned* ei) {
    unsigned hi = ei[2 * threadIdx.x + 1];
    unsigned any = __ballot_sync(0xffffffffu, hi != 0u);
    if (threadIdx.x == 0) g_ei64 = (any == 0u) ? 1 : 0;
}

// --- bin edges by src bucket (block-staged cursors) + degree REDs ----------
#define BIN_T 256
#define EPT   16
#define EPB   (BIN_T * EPT)   // 4096 edges per block

__global__ void k_bin(const void* ei, int E, int NB) {
    __shared__ int s_cnt[NBMAX];
    __shared__ int s_base[NBMAX];
    int tid = threadIdx.x;
    for (int b = tid; b < NB; b += BIN_T) s_cnt[b] = 0;
    __syncthreads();

    int e0 = blockIdx.x * EPB + tid * EPT;
    int cnt_t = E - e0; if (cnt_t > EPT) cnt_t = EPT; if (cnt_t < 0) cnt_t = 0;

    int s[EPT], d[EPT], sl[EPT];
    if (cnt_t == EPT) {
        if (g_ei64) {
            const longlong2* ps = (const longlong2*)((const long long*)ei + e0);
            const longlong2* pd = (const longlong2*)((const long long*)ei + E + e0);
#pragma unroll
            for (int j = 0; j < EPT / 2; j++) {
                longlong2 a = __ldg(ps + j); longlong2 bb = __ldg(pd + j);
                s[2*j] = (int)a.x; s[2*j+1] = (int)a.y;
                d[2*j] = (int)bb.x; d[2*j+1] = (int)bb.y;
            }
        } else {
            const int4* ps = (const int4*)((const int*)ei + e0);
            const int4* pd = (const int4*)((const int*)ei + E + e0);
#pragma unroll
            for (int j = 0; j < EPT / 4; j++) {
                int4 a = __ldg(ps + j); int4 bb = __ldg(pd + j);
                s[4*j] = a.x; s[4*j+1] = a.y; s[4*j+2] = a.z; s[4*j+3] = a.w;
                d[4*j] = bb.x; d[4*j+1] = bb.y; d[4*j+2] = bb.z; d[4*j+3] = bb.w;
            }
        }
    } else {
        for (int j = 0; j < cnt_t; j++) {
            if (g_ei64) {
                const long long* p = (const long long*)ei;
                s[j] = (int)__ldg(p + e0 + j); d[j] = (int)__ldg(p + E + e0 + j);
            } else {
                const int* p = (const int*)ei;
                s[j] = __ldg(p + e0 + j); d[j] = __ldg(p + E + e0 + j);
            }
        }
    }
#pragma unroll
    for (int j = 0; j < EPT; j++) {
        if (j >= cnt_t) break;
        sl[j] = atomicAdd(&s_cnt[s[j] >> NBITS], 1);
        REDI(&g_deg[d[j]]);                    // fused in-degree count
    }
    __syncthreads();
    for (int b = tid; b < NB; b += BIN_T) {
        int c = s_cnt[b];
        s_base[b] = c ? atomicAdd(&g_cursor[b], c) : 0;
    }
    __syncthreads();
#pragma unroll
    for (int j = 0; j < EPT; j++) {
        if (j >= cnt_t) break;
        int b = s[j] >> NBITS;
        int slot = s_base[b] + sl[j];
        if (slot < CAP)
            g_bins[b * CAP + slot] =
                ((unsigned)(s[j] - (b << NBITS)) << 20) | (unsigned)d[j];
    }
}

// --- node pass 1: dinv = rsqrt(deg+1), xs = x*dinv, a1 = xs ---------------
__global__ void k_l1(const float* __restrict__ x, int N) {
    int i = blockIdx.x * blockDim.x + threadIdx.x;
    if (i >= N) return;
    float4 xv = __ldg(&((const float4*)x)[i]);
    float di = rsqrtf((float)(g_deg[i] + 1));   // +1 = self loop
    g_dinv[i] = di;
    float4 v = make_float4(xv.x * di, xv.y * di, xv.z * di, xv.w * di);
    ((float4*)g_xs)[i] = v;
    ((float4*)g_a1)[i] = v;  // self-loop contribution
}

// --- layer-1 scatter: SMEM-staged gather, global RED4 ---------------------
__global__ void k_s1(int N) {
    __shared__ float4 s_xs[BSZ];               // 32 KB
    int b = blockIdx.x, tid = threadIdx.x;
    int nb0 = b << NBITS;
    for (int i = tid; i < BSZ; i += blockDim.x) {
        int node = nb0 + i;
        s_xs[i] = (node < N) ? ((const float4*)g_xs)[node]
                             : make_float4(0.f, 0.f, 0.f, 0.f);
    }
    __syncthreads();
    int cnt = g_cursor[b]; if (cnt > CAP) cnt = CAP;
    const unsigned* bin = &g_bins[(size_t)b * CAP];
    for (int e = tid; e < cnt; e += blockDim.x) {
        unsigned u = __ldg(bin + e);
        float4 v = s_xs[u >> 20];
        RED4(u & 0xFFFFFu, v);
    }
}

// --- node pass 2: h = relu(dinv*(a1@W1)+b1); h2 = (h@W2)*dinv; a2 = h2 ----
__global__ void k_l2(const float* __restrict__ W1, const float* __restrict__ b1,
                     const float* __restrict__ W2, int N) {
    __shared__ float sW1[64], sb1[16], sW2[32];
    int tid = threadIdx.x;
    if (tid < 64)              sW1[tid]      = W1[tid];
    else if (tid < 80)         sb1[tid - 64] = b1[tid - 64];
    else if (tid < 112)        sW2[tid - 80] = W2[tid - 80];
    __syncthreads();

    int i = blockIdx.x * blockDim.x + tid;
    if (i >= N) return;
    float di = g_dinv[i];
    float4 av = ((const float4*)g_a1)[i];   // includes self loop
    float o0 = 0.f, o1 = 0.f;
#pragma unroll
    for (int k = 0; k < 16; k++) {
        float h = di * (av.x * sW1[k]      + av.y * sW1[16 + k] +
                        av.z * sW1[32 + k] + av.w * sW1[48 + k]) + sb1[k];
        h = fmaxf(h, 0.f);
        o0 += h * sW2[2 * k];
        o1 += h * sW2[2 * k + 1];
    }
    float2 v = make_float2(o0 * di, o1 * di);
    ((float2*)g_h2)[i] = v;
    ((float2*)g_a2)[i] = v;  // self-loop contribution
}

// --- layer-2 scatter: SMEM-staged gather, global RED2 ---------------------
__global__ void k_s2(int N) {
    __shared__ float2 s_h2[BSZ];               // 16 KB
    int b = blockIdx.x, tid = threadIdx.x;
    int nb0 = b << NBITS;
    for (int i = tid; i < BSZ; i += blockDim.x) {
        int node = nb0 + i;
        s_h2[i] = (node < N) ? ((const float2*)g_h2)[node] : make_float2(0.f, 0.f);
    }
    __syncthreads();
    int cnt = g_cursor[b]; if (cnt > CAP) cnt = CAP;
    const unsigned* bin = &g_bins[(size_t)b * CAP];
    for (int e = tid; e < cnt; e += blockDim.x) {
        unsigned u = __ldg(bin + e);
        float2 v = s_h2[u >> 20];
        RED2(u & 0xFFFFFu, v);
    }
}

// --- output: o = dinv*a2 + b2; log_softmax over 2 classes -----------------
__global__ void k_out(const float* __restrict__ b2, float* __restrict__ out, int N) {
    int i = blockIdx.x * blockDim.x + threadIdx.x;
    if (i >= N) return;
    float di = g_dinv[i];
    float2 a = ((const float2*)g_a2)[i];    // includes self loop
    float2 bb = __ldg((const float2*)b2);
    float o0 = di * a.x + bb.x;
    float o1 = di * a.y + bb.y;
    float m = fmaxf(o0, o1);
    float ls = m + __logf(__expf(o0 - m) + __expf(o1 - m));
    ((float2*)out)[i] = make_float2(o0 - ls, o1 - ls);
}

extern "C" void kernel_launch(void* const* d_in, const int* in_sizes, int n_in,
                              void* d_out, int out_size) {
    const float* x  = (const float*)d_in[0];
    const void*  ei = d_in[1];
    int wi = 2;
    if (n_in >= 7 && in_sizes[2] < 16) wi = 3;  // skip num_nodes scalar
    const float* W1 = (const float*)d_in[wi];
    const float* b1 = (const float*)d_in[wi + 1];
    const float* W2 = (const float*)d_in[wi + 2];
    const float* b2 = (const float*)d_in[wi + 3];

    int N = in_sizes[0] / 4;
    int E = in_sizes[1] / 2;
    int NB = (N + BSZ - 1) >> NBITS;
    if (NB > NBMAX) NB = NBMAX;

    const int T = 256;
    int gN = (N + T - 1) / T;

    void *curp = nullptr, *degp = nullptr;
    cudaGetSymbolAddress(&curp, g_cursor);
    cudaGetSymbolAddress(&degp, g_deg);

    k_detect<<<1, 32>>>((const unsigned*)ei);
    cudaMemsetAsync(curp, 0, (size_t)NB * sizeof(int));
    cudaMemsetAsync(degp, 0, (size_t)N * sizeof(int));
    k_bin<<<(E + EPB - 1) / EPB, BIN_T>>>(ei, E, NB);
    k_l1<<<gN, T>>>(x, N);
    k_s1<<<NB, 512>>>(N);
    k_l2<<<gN, T>>>(W1, b1, W2, N);
    k_s2<<<NB, 512>>>(N);
    k_out<<<gN, T>>>(b2, (float*)d_out, N);
}

// round 9
// speedup vs baseline: 1.6117x; 1.2266x over previous
#include <cuda_runtime.h>
#include <cuda_bf16.h>
#include <math.h>

// ---------------------------------------------------------------------------
// 2-layer GCN, N=1M, E=4M, 4 -> 16 -> 2, log_softmax.
// Flat R4 pipeline + forked-stream prologue:
//   branchA: deg(dst col) -> l1 (xs, a1=self-loop)
//   branchB: pack edges -> int2
// then sc1 -> l2 -> sc2 -> out. Scatters use global red.v4/v2 (L2-parallel).
// ---------------------------------------------------------------------------

#define NMAX 1048576
#define EMAX 4194304

__device__ int2  g_edges[EMAX];      // packed (src, dst)
__device__ int   g_deg  [NMAX];
__device__ float g_dinv [NMAX];
__device__ float g_xs   [NMAX * 4];  // x * dinv
__device__ float g_a1   [NMAX * 4];  // layer-1 acc, init = xs (self loop)
__device__ float g_h2   [NMAX * 2];  // (h@W2)*dinv
__device__ float g_a2   [NMAX * 2];  // layer-2 acc, init = h2 (self loop)
__device__ int   g_ei64;

#define RED4(idx, v) \
    asm volatile("red.global.add.v4.f32 [%0], {%1,%2,%3,%4};" \
                 :: "l"(&((float4*)g_a1)[idx]), "f"((v).x), "f"((v).y), "f"((v).z), "f"((v).w) : "memory")
#define RED2(idx, v) \
    asm volatile("red.global.add.v2.f32 [%0], {%1,%2};" \
                 :: "l"(&((float2*)g_a2)[idx]), "f"((v).x), "f"((v).y) : "memory")
#define REDI(p) \
    asm volatile("red.global.add.u32 [%0], %1;" :: "l"(p), "r"(1) : "memory")

// --- dtype detection: int64 indices < 2^20 have all-zero high words --------
__global__ void k_detect(const unsigned* ei) {
    unsigned hi = ei[2 * threadIdx.x + 1];
    unsigned any = __ballot_sync(0xffffffffu, hi != 0u);
    if (threadIdx.x == 0) g_ei64 = (any == 0u) ? 1 : 0;
}

// --- degree pass: reads ONLY the dst column (4 edges/thread) ---------------
__global__ void k_deg(const void* ei, int E) {
    int t = blockIdx.x * blockDim.x + threadIdx.x;
    int e0 = t * 4;
    if (e0 >= E) return;
    if (e0 + 3 < E) {
        int d[4];
        if (g_ei64) {
            const long long* p = (const long long*)ei + E;
            longlong2 da = __ldg((const longlong2*)(p + e0));
            longlong2 db = __ldg((const longlong2*)(p + e0 + 2));
            d[0] = (int)da.x; d[1] = (int)da.y; d[2] = (int)db.x; d[3] = (int)db.y;
        } else {
            const int* p = (const int*)ei + E;
            int4 dd = __ldg((const int4*)(p + e0));
            d[0] = dd.x; d[1] = dd.y; d[2] = dd.z; d[3] = dd.w;
        }
        REDI(&g_deg[d[0]]); REDI(&g_deg[d[1]]);
        REDI(&g_deg[d[2]]); REDI(&g_deg[d[3]]);
    } else {
        for (int e = e0; e < E; e++) {
            int d;
            if (g_ei64) d = (int)__ldg((const long long*)ei + E + e);
            else        d = __ldg((const int*)ei + E + e);
            REDI(&g_deg[d]);
        }
    }
}

// --- pack pass: both columns -> int2 g_edges (4 edges/thread) --------------
__global__ void k_pack(const void* ei, int E) {
    int t = blockIdx.x * blockDim.x + threadIdx.x;
    int e0 = t * 4;
    if (e0 >= E) return;
    if (e0 + 3 < E) {
        int s[4], d[4];
        if (g_ei64) {
            const long long* p = (const long long*)ei;
            longlong2 sa = __ldg((const longlong2*)(p + e0));
            longlong2 sb = __ldg((const longlong2*)(p + e0 + 2));
            longlong2 da = __ldg((const longlong2*)(p + E + e0));
            longlong2 db = __ldg((const longlong2*)(p + E + e0 + 2));
            s[0] = (int)sa.x; s[1] = (int)sa.y; s[2] = (int)sb.x; s[3] = (int)sb.y;
            d[0] = (int)da.x; d[1] = (int)da.y; d[2] = (int)db.x; d[3] = (int)db.y;
        } else {
            const int* p = (const int*)ei;
            int4 ss = __ldg((const int4*)(p + e0));
            int4 dd = __ldg((const int4*)(p + E + e0));
            s[0] = ss.x; s[1] = ss.y; s[2] = ss.z; s[3] = ss.w;
            d[0] = dd.x; d[1] = dd.y; d[2] = dd.z; d[3] = dd.w;
        }
        ((int4*)g_edges)[t * 2]     = make_int4(s[0], d[0], s[1], d[1]);
        ((int4*)g_edges)[t * 2 + 1] = make_int4(s[2], d[2], s[3], d[3]);
    } else {
        for (int e = e0; e < E; e++) {
            int s, d;
            if (g_ei64) {
                const long long* p = (const long long*)ei;
                s = (int)__ldg(p + e); d = (int)__ldg(p + E + e);
            } else {
                const int* p = (const int*)ei;
                s = __ldg(p + e); d = __ldg(p + E + e);
            }
            g_edges[e] = make_int2(s, d);
        }
    }
}

// --- node pass 1: dinv = rsqrt(deg+1), xs = x*dinv, a1 = xs ---------------
__global__ void k_l1(const float* __restrict__ x, int N) {
    int i = blockIdx.x * blockDim.x + threadIdx.x;
    if (i >= N) return;
    float4 xv = __ldg(&((const float4*)x)[i]);
    float di = rsqrtf((float)(g_deg[i] + 1));   // +1 = self loop
    g_dinv[i] = di;
    float4 v = make_float4(xv.x * di, xv.y * di, xv.z * di, xv.w * di);
    ((float4*)g_xs)[i] = v;
    ((float4*)g_a1)[i] = v;  // self-loop contribution
}

// --- layer-1 edge scatter: a1[dst] += xs[src] (4 edges/thread) ------------
__global__ void k_sc1(int E) {
    int t = blockIdx.x * blockDim.x + threadIdx.x;
    int e0 = t * 4;
    if (e0 >= E) return;
    if (e0 + 3 < E) {
        int4 ea = ((const int4*)g_edges)[t * 2];
        int4 eb = ((const int4*)g_edges)[t * 2 + 1];
        float4 v0 = __ldg(&((const float4*)g_xs)[ea.x]);
        float4 v1 = __ldg(&((const float4*)g_xs)[ea.z]);
        float4 v2 = __ldg(&((const float4*)g_xs)[eb.x]);
        float4 v3 = __ldg(&((const float4*)g_xs)[eb.z]);
        RED4(ea.y, v0); RED4(ea.w, v1); RED4(eb.y, v2); RED4(eb.w, v3);
    } else {
        for (int e = e0; e < E; e++) {
            int2 sd = g_edges[e];
            float4 v = __ldg(&((const float4*)g_xs)[sd.x]);
            RED4(sd.y, v);
        }
    }
}

// --- node pass 2: h = relu(dinv*(a1@W1)+b1); h2 = (h@W2)*dinv; a2 = h2 ----
__global__ void k_l2(const float* __restrict__ W1, const float* __restrict__ b1,
                     const float* __restrict__ W2, int N) {
    __shared__ float sW1[64], sb1[16], sW2[32];
    int tid = threadIdx.x;
    if (tid < 64)              sW1[tid]      = W1[tid];
    else if (tid < 80)         sb1[tid - 64] = b1[tid - 64];
    else if (tid < 112)        sW2[tid - 80] = W2[tid - 80];
    __syncthreads();

    int i = blockIdx.x * blockDim.x + tid;
    if (i >= N) return;
    float di = g_dinv[i];
    float4 av = ((const float4*)g_a1)[i];   // includes self loop
    float o0 = 0.f, o1 = 0.f;
#pragma unroll
    for (int k = 0; k < 16; k++) {
        float h = di * (av.x * sW1[k]      + av.y * sW1[16 + k] +
                        av.z * sW1[32 + k] + av.w * sW1[48 + k]) + sb1[k];
        h = fmaxf(h, 0.f);
        o0 += h * sW2[2 * k];
        o1 += h * sW2[2 * k + 1];
    }
    float2 v = make_float2(o0 * di, o1 * di);
    ((float2*)g_h2)[i] = v;
    ((float2*)g_a2)[i] = v;  // self-loop contribution
}

// --- layer-2 edge scatter: a2[dst] += h2[src] (4 edges/thread) ------------
__global__ void k_sc2(int E) {
    int t = blockIdx.x * blockDim.x + threadIdx.x;
    int e0 = t * 4;
    if (e0 >= E) return;
    if (e0 + 3 < E) {
        int4 ea = ((const int4*)g_edges)[t * 2];
        int4 eb = ((const int4*)g_edges)[t * 2 + 1];
        float2 v0 = __ldg(&((const float2*)g_h2)[ea.x]);
        float2 v1 = __ldg(&((const float2*)g_h2)[ea.z]);
        float2 v2 = __ldg(&((const float2*)g_h2)[eb.x]);
        float2 v3 = __ldg(&((const float2*)g_h2)[eb.z]);
        RED2(ea.y, v0); RED2(ea.w, v1); RED2(eb.y, v2); RED2(eb.w, v3);
    } else {
        for (int e = e0; e < E; e++) {
            int2 sd = g_edges[e];
            float2 v = __ldg(&((const float2*)g_h2)[sd.x]);
            RED2(sd.y, v);
        }
    }
}

// --- output: o = dinv*a2 + b2; log_softmax over 2 classes -----------------
__global__ void k_out(const float* __restrict__ b2, float* __restrict__ out, int N) {
    int i = blockIdx.x * blockDim.x + threadIdx.x;
    if (i >= N) return;
    float di = g_dinv[i];
    float2 a = ((const float2*)g_a2)[i];    // includes self loop
    float2 bb = __ldg((const float2*)b2);
    float o0 = di * a.x + bb.x;
    float o1 = di * a.y + bb.y;
    float m = fmaxf(o0, o1);
    float ls = m + __logf(__expf(o0 - m) + __expf(o1 - m));
    ((float2*)out)[i] = make_float2(o0 - ls, o1 - ls);
}

extern "C" void kernel_launch(void* const* d_in, const int* in_sizes, int n_in,
                              void* d_out, int out_size) {
    const float* x  = (const float*)d_in[0];
    const void*  ei = d_in[1];
    int wi = 2;
    if (n_in >= 7 && in_sizes[2] < 16) wi = 3;  // skip num_nodes scalar
    const float* W1 = (const float*)d_in[wi];
    const float* b1 = (const float*)d_in[wi + 1];
    const float* W2 = (const float*)d_in[wi + 2];
    const float* b2 = (const float*)d_in[wi + 3];

    int N = in_sizes[0] / 4;
    int E = in_sizes[1] / 2;

    const int T = 256;
    int gN  = (N + T - 1) / T;
    int gE4 = ((E + 3) / 4 + T - 1) / T;

    void* degp = nullptr;
    cudaGetSymbolAddress(&degp, g_deg);

    cudaStream_t s1;
    cudaStreamCreateWithFlags(&s1, cudaStreamNonBlocking);
    cudaEvent_t evFork, evJoin;
    cudaEventCreateWithFlags(&evFork, cudaEventDisableTiming);
    cudaEventCreateWithFlags(&evJoin, cudaEventDisableTiming);

    // prologue on main stream
    k_detect<<<1, 32>>>((const unsigned*)ei);
    cudaEventRecord(evFork, 0);
    cudaStreamWaitEvent(s1, evFork, 0);

    // branch A (main stream): degrees -> node pass 1
    cudaMemsetAsync(degp, 0, (size_t)N * sizeof(int));
    k_deg<<<gE4, T>>>(ei, E);
    k_l1<<<gN, T>>>(x, N);

    // branch B (side stream): pack edge list
    k_pack<<<gE4, T, 0, s1>>>(ei, E);
    cudaEventRecord(evJoin, s1);
    cudaStreamWaitEvent(0, evJoin, 0);

    // main chain
    k_sc1<<<gE4, T>>>(E);
    k_l2<<<gN, T>>>(W1, b1, W2, N);
    k_sc2<<<gE4, T>>>(E);
    k_out<<<gN, T>>>(b2, (float*)d_out, N);

    cudaEventDestroy(evFork);
    cudaEventDestroy(evJoin);
    cudaStreamDestroy(s1);
}

// round 10
// speedup vs baseline: 1.7075x; 1.0594x over previous
#include <cuda_runtime.h>
#include <cuda_bf16.h>
#include <math.h>

// ---------------------------------------------------------------------------
// 2-layer GCN, N=1M, E=4M, 4 -> 16 -> 2, log_softmax.
// Dtype-adaptive: int32 edge_index is consumed IN PLACE (no pack pass);
// int64 is packed to int2 on a side stream (hidden under deg+l1).
// Scatters: 4 edges/thread, gather + global red.v4/v2 (L2-slice parallel).
// ---------------------------------------------------------------------------

#define NMAX 1048576
#define EMAX 4194304

__device__ int2  g_edges[EMAX];      // packed (src, dst) — int64 path only
__device__ int   g_deg  [NMAX];
__device__ float g_dinv [NMAX];
__device__ float g_xs   [NMAX * 4];  // x * dinv
__device__ float g_a1   [NMAX * 4];  // layer-1 acc, init = xs (self loop)
__device__ float g_h2   [NMAX * 2];  // (h@W2)*dinv
__device__ float g_a2   [NMAX * 2];  // layer-2 acc, init = h2 (self loop)
__device__ int   g_ei64;

#define RED4(idx, v) \
    asm volatile("red.global.add.v4.f32 [%0], {%1,%2,%3,%4};" \
                 :: "l"(&((float4*)g_a1)[idx]), "f"((v).x), "f"((v).y), "f"((v).z), "f"((v).w) : "memory")
#define RED2(idx, v) \
    asm volatile("red.global.add.v2.f32 [%0], {%1,%2};" \
                 :: "l"(&((float2*)g_a2)[idx]), "f"((v).x), "f"((v).y) : "memory")
#define REDI(p) \
    asm volatile("red.global.add.u32 [%0], %1;" :: "l"(p), "r"(1) : "memory")

// --- dtype detection: int64 indices < 2^20 have all-zero high words --------
__global__ void k_detect(const unsigned* ei) {
    unsigned hi = ei[2 * threadIdx.x + 1];
    unsigned any = __ballot_sync(0xffffffffu, hi != 0u);
    if (threadIdx.x == 0) g_ei64 = (any == 0u) ? 1 : 0;
}

// --- degree pass: reads ONLY the raw dst column (4 edges/thread) -----------
__global__ void k_deg(const void* ei, int E) {
    int t = blockIdx.x * blockDim.x + threadIdx.x;
    int e0 = t * 4;
    if (e0 >= E) return;
    if (e0 + 3 < E) {
        int d[4];
        if (g_ei64) {
            const long long* p = (const long long*)ei + E;
            longlong2 da = __ldg((const longlong2*)(p + e0));
            longlong2 db = __ldg((const longlong2*)(p + e0 + 2));
            d[0] = (int)da.x; d[1] = (int)da.y; d[2] = (int)db.x; d[3] = (int)db.y;
        } else {
            const int* p = (const int*)ei + E;
            int4 dd = __ldg((const int4*)(p + e0));
            d[0] = dd.x; d[1] = dd.y; d[2] = dd.z; d[3] = dd.w;
        }
        REDI(&g_deg[d[0]]); REDI(&g_deg[d[1]]);
        REDI(&g_deg[d[2]]); REDI(&g_deg[d[3]]);
    } else {
        for (int e = e0; e < E; e++) {
            int d;
            if (g_ei64) d = (int)__ldg((const long long*)ei + E + e);
            else        d = __ldg((const int*)ei + E + e);
            REDI(&g_deg[d]);
        }
    }
}

// --- pack pass (int64 path only; no-op for int32) --------------------------
__global__ void k_pack(const void* ei, int E) {
    if (!g_ei64) return;
    int t = blockIdx.x * blockDim.x + threadIdx.x;
    int e0 = t * 4;
    if (e0 >= E) return;
    const long long* p = (const long long*)ei;
    if (e0 + 3 < E) {
        longlong2 sa = __ldg((const longlong2*)(p + e0));
        longlong2 sb = __ldg((const longlong2*)(p + e0 + 2));
        longlong2 da = __ldg((const longlong2*)(p + E + e0));
        longlong2 db = __ldg((const longlong2*)(p + E + e0 + 2));
        ((int4*)g_edges)[t * 2]     = make_int4((int)sa.x, (int)da.x, (int)sa.y, (int)da.y);
        ((int4*)g_edges)[t * 2 + 1] = make_int4((int)sb.x, (int)db.x, (int)sb.y, (int)db.y);
    } else {
        for (int e = e0; e < E; e++)
            g_edges[e] = make_int2((int)__ldg(p + e), (int)__ldg(p + E + e));
    }
}

// --- edge fetch helper for scatters: 4 edges -------------------------------
__device__ __forceinline__ void fetch4(const void* ei, int E, int t,
                                       int* s, int* d) {
    if (g_ei64) {
        int4 ea = ((const int4*)g_edges)[t * 2];
        int4 eb = ((const int4*)g_edges)[t * 2 + 1];
        s[0] = ea.x; d[0] = ea.y; s[1] = ea.z; d[1] = ea.w;
        s[2] = eb.x; d[2] = eb.y; s[3] = eb.z; d[3] = eb.w;
    } else {
        const int* p = (const int*)ei;
        int4 ss = __ldg((const int4*)(p + t * 4));
        int4 dd = __ldg((const int4*)(p + E + t * 4));
        s[0] = ss.x; s[1] = ss.y; s[2] = ss.z; s[3] = ss.w;
        d[0] = dd.x; d[1] = dd.y; d[2] = dd.z; d[3] = dd.w;
    }
}

__device__ __forceinline__ void fetch1(const void* ei, int E, int e,
                                       int& s, int& d) {
    if (g_ei64) {
        int2 sd = g_edges[e];
        s = sd.x; d = sd.y;
    } else {
        const int* p = (const int*)ei;
        s = __ldg(p + e); d = __ldg(p + E + e);
    }
}

// --- node pass 1: dinv = rsqrt(deg+1), xs = x*dinv, a1 = xs ---------------
__global__ void k_l1(const float* __restrict__ x, int N) {
    int i = blockIdx.x * blockDim.x + threadIdx.x;
    if (i >= N) return;
    float4 xv = __ldg(&((const float4*)x)[i]);
    float di = rsqrtf((float)(g_deg[i] + 1));   // +1 = self loop
    g_dinv[i] = di;
    float4 v = make_float4(xv.x * di, xv.y * di, xv.z * di, xv.w * di);
    ((float4*)g_xs)[i] = v;
    ((float4*)g_a1)[i] = v;  // self-loop contribution
}

// --- layer-1 edge scatter: a1[dst] += xs[src] (4 edges/thread) ------------
__global__ void k_sc1(const void* ei, int E) {
    int t = blockIdx.x * blockDim.x + threadIdx.x;
    int e0 = t * 4;
    if (e0 >= E) return;
    if (e0 + 3 < E) {
        int s[4], d[4];
        fetch4(ei, E, t, s, d);
        float4 v0 = __ldg(&((const float4*)g_xs)[s[0]]);
        float4 v1 = __ldg(&((const float4*)g_xs)[s[1]]);
        float4 v2 = __ldg(&((const float4*)g_xs)[s[2]]);
        float4 v3 = __ldg(&((const float4*)g_xs)[s[3]]);
        RED4(d[0], v0); RED4(d[1], v1); RED4(d[2], v2); RED4(d[3], v3);
    } else {
        for (int e = e0; e < E; e++) {
            int s, d;
            fetch1(ei, E, e, s, d);
            float4 v = __ldg(&((const float4*)g_xs)[s]);
            RED4(d, v);
        }
    }
}

// --- node pass 2: h = relu(dinv*(a1@W1)+b1); h2 = (h@W2)*dinv; a2 = h2 ----
__global__ void k_l2(const float* __restrict__ W1, const float* __restrict__ b1,
                     const float* __restrict__ W2, int N) {
    __shared__ float sW1[64], sb1[16], sW2[32];
    int tid = threadIdx.x;
    if (tid < 64)              sW1[tid]      = W1[tid];
    else if (tid < 80)         sb1[tid - 64] = b1[tid - 64];
    else if (tid < 112)        sW2[tid - 80] = W2[tid - 80];
    __syncthreads();

    int i = blockIdx.x * blockDim.x + tid;
    if (i >= N) return;
    float di = g_dinv[i];
    float4 av = ((const float4*)g_a1)[i];   // includes self loop
    float o0 = 0.f, o1 = 0.f;
#pragma unroll
    for (int k = 0; k < 16; k++) {
        float h = di * (av.x * sW1[k]      + av.y * sW1[16 + k] +
                        av.z * sW1[32 + k] + av.w * sW1[48 + k]) + sb1[k];
        h = fmaxf(h, 0.f);
        o0 += h * sW2[2 * k];
        o1 += h * sW2[2 * k + 1];
    }
    float2 v = make_float2(o0 * di, o1 * di);
    ((float2*)g_h2)[i] = v;
    ((float2*)g_a2)[i] = v;  // self-loop contribution
}

// --- layer-2 edge scatter: a2[dst] += h2[src] (4 edges/thread) ------------
__global__ void k_sc2(const void* ei, int E) {
    int t = blockIdx.x * blockDim.x + threadIdx.x;
    int e0 = t * 4;
    if (e0 >= E) return;
    if (e0 + 3 < E) {
        int s[4], d[4];
        fetch4(ei, E, t, s, d);
        float2 v0 = __ldg(&((const float2*)g_h2)[s[0]]);
        float2 v1 = __ldg(&((const float2*)g_h2)[s[1]]);
        float2 v2 = __ldg(&((const float2*)g_h2)[s[2]]);
        float2 v3 = __ldg(&((const float2*)g_h2)[s[3]]);
        RED2(d[0], v0); RED2(d[1], v1); RED2(d[2], v2); RED2(d[3], v3);
    } else {
        for (int e = e0; e < E; e++) {
            int s, d;
            fetch1(ei, E, e, s, d);
            float2 v = __ldg(&((const float2*)g_h2)[s]);
            RED2(d, v);
        }
    }
}

// --- output: o = dinv*a2 + b2; log_softmax over 2 classes -----------------
__global__ void k_out(const float* __restrict__ b2, float* __restrict__ out, int N) {
    int i = blockIdx.x * blockDim.x + threadIdx.x;
    if (i >= N) return;
    float di = g_dinv[i];
    float2 a = ((const float2*)g_a2)[i];    // includes self loop
    float2 bb = __ldg((const float2*)b2);
    float o0 = di * a.x + bb.x;
    float o1 = di * a.y + bb.y;
    float m = fmaxf(o0, o1);
    float ls = m + __logf(__expf(o0 - m) + __expf(o1 - m));
    ((float2*)out)[i] = make_float2(o0 - ls, o1 - ls);
}

extern "C" void kernel_launch(void* const* d_in, const int* in_sizes, int n_in,
                              void* d_out, int out_size) {
    const float* x  = (const float*)d_in[0];
    const void*  ei = d_in[1];
    int wi = 2;
    if (n_in >= 7 && in_sizes[2] < 16) wi = 3;  // skip num_nodes scalar
    const float* W1 = (const float*)d_in[wi];
    const float* b1 = (const float*)d_in[wi + 1];
    const float* W2 = (const float*)d_in[wi + 2];
    const float* b2 = (const float*)d_in[wi + 3];

    int N = in_sizes[0] / 4;
    int E = in_sizes[1] / 2;

    const int T = 256;
    int gN  = (N + T - 1) / T;
    int gE4 = ((E + 3) / 4 + T - 1) / T;

    void* degp = nullptr;
    cudaGetSymbolAddress(&degp, g_deg);

    cudaStream_t s1;
    cudaStreamCreateWithFlags(&s1, cudaStreamNonBlocking);
    cudaEvent_t evFork, evJoin;
    cudaEventCreateWithFlags(&evFork, cudaEventDisableTiming);
    cudaEventCreateWithFlags(&evJoin, cudaEventDisableTiming);

    k_detect<<<1, 32>>>((const unsigned*)ei);
    cudaEventRecord(evFork, 0);
    cudaStreamWaitEvent(s1, evFork, 0);

    // branch A (main): degrees -> node pass 1
    cudaMemsetAsync(degp, 0, (size_t)N * sizeof(int));
    k_deg<<<gE4, T>>>(ei, E);
    k_l1<<<gN, T>>>(x, N);

    // branch B (side): pack (int64 only; early-exit for int32)
    k_pack<<<gE4, T, 0, s1>>>(ei, E);
    cudaEventRecord(evJoin, s1);
    cudaStreamWaitEvent(0, evJoin, 0);

    k_sc1<<<gE4, T>>>(ei, E);
    k_l2<<<gN, T>>>(W1, b1, W2, N);
    k_sc2<<<gE4, T>>>(ei, E);
    k_out<<<gN, T>>>(b2, (float*)d_out, N);

    cudaEventDestroy(evFork);
    cudaEventDestroy(evJoin);
    cudaStreamDestroy(s1);
}

// round 11
// speedup vs baseline: 1.7972x; 1.0525x over previous
#include <cuda_runtime.h>
#include <cuda_bf16.h>
#include <math.h>

// ---------------------------------------------------------------------------
// 2-layer GCN, N=1M, E=4M, 4 -> 16 -> 2, log_softmax.
// Dtype-adaptive (int32 consumed in place; int64 packed on side stream).
// PDL chain: consumers prefetch independent streams (edges / x / weights)
// before cudaGridDependencySynchronize, overlapping producer tails.
// ---------------------------------------------------------------------------

#define NMAX 1048576
#define EMAX 4194304

__device__ int2  g_edges[EMAX];      // packed (src, dst) — int64 path only
__device__ int   g_deg  [NMAX];
__device__ float g_dinv [NMAX];
__device__ float g_xs   [NMAX * 4];  // x * dinv
__device__ float g_a1   [NMAX * 4];  // layer-1 acc, init = xs (self loop)
__device__ float g_h2   [NMAX * 2];  // (h@W2)*dinv
__device__ float g_a2   [NMAX * 2];  // layer-2 acc, init = h2 (self loop)
__device__ int   g_ei64;

#define RED4(idx, v) \
    asm volatile("red.global.add.v4.f32 [%0], {%1,%2,%3,%4};" \
                 :: "l"(&((float4*)g_a1)[idx]), "f"((v).x), "f"((v).y), "f"((v).z), "f"((v).w) : "memory")
#define RED2(idx, v) \
    asm volatile("red.global.add.v2.f32 [%0], {%1,%2};" \
                 :: "l"(&((float2*)g_a2)[idx]), "f"((v).x), "f"((v).y) : "memory")
#define REDI(p) \
    asm volatile("red.global.add.u32 [%0], %1;" :: "l"(p), "r"(1) : "memory")

__device__ __forceinline__ void pdl_trigger() {
#if defined(__CUDA_ARCH__) && __CUDA_ARCH__ >= 900
    cudaTriggerProgrammaticLaunchCompletion();
#endif
}
__device__ __forceinline__ void pdl_wait() {
#if defined(__CUDA_ARCH__) && __CUDA_ARCH__ >= 900
    cudaGridDependencySynchronize();
#endif
}

// --- dtype detection: int64 indices < 2^20 have all-zero high words --------
__global__ void k_detect(const unsigned* ei) {
    unsigned hi = ei[2 * threadIdx.x + 1];
    unsigned any = __ballot_sync(0xffffffffu, hi != 0u);
    if (threadIdx.x == 0) g_ei64 = (any == 0u) ? 1 : 0;
}

// --- degree pass: reads ONLY the raw dst column (4 edges/thread) -----------
__global__ void k_deg(const void* ei, int E) {
    int t = blockIdx.x * blockDim.x + threadIdx.x;
    int e0 = t * 4;
    if (e0 < E) {
        if (e0 + 3 < E) {
            int d[4];
            if (g_ei64) {
                const long long* p = (const long long*)ei + E;
                longlong2 da = __ldg((const longlong2*)(p + e0));
                longlong2 db = __ldg((const longlong2*)(p + e0 + 2));
                d[0] = (int)da.x; d[1] = (int)da.y; d[2] = (int)db.x; d[3] = (int)db.y;
            } else {
                const int* p = (const int*)ei + E;
                int4 dd = __ldg((const int4*)(p + e0));
                d[0] = dd.x; d[1] = dd.y; d[2] = dd.z; d[3] = dd.w;
            }
            REDI(&g_deg[d[0]]); REDI(&g_deg[d[1]]);
            REDI(&g_deg[d[2]]); REDI(&g_deg[d[3]]);
        } else {
            for (int e = e0; e < E; e++) {
                int d;
                if (g_ei64) d = (int)__ldg((const long long*)ei + E + e);
                else        d = __ldg((const int*)ei + E + e);
                REDI(&g_deg[d]);
            }
        }
    }
    pdl_trigger();
}

// --- pack pass (int64 path only; no-op for int32) --------------------------
__global__ void k_pack(const void* ei, int E) {
    if (!g_ei64) return;
    int t = blockIdx.x * blockDim.x + threadIdx.x;
    int e0 = t * 4;
    if (e0 >= E) return;
    const long long* p = (const long long*)ei;
    if (e0 + 3 < E) {
        longlong2 sa = __ldg((const longlong2*)(p + e0));
        longlong2 sb = __ldg((const longlong2*)(p + e0 + 2));
        longlong2 da = __ldg((const longlong2*)(p + E + e0));
        longlong2 db = __ldg((const longlong2*)(p + E + e0 + 2));
        ((int4*)g_edges)[t * 2]     = make_int4((int)sa.x, (int)da.x, (int)sa.y, (int)da.y);
        ((int4*)g_edges)[t * 2 + 1] = make_int4((int)sb.x, (int)db.x, (int)sb.y, (int)db.y);
    } else {
        for (int e = e0; e < E; e++)
            g_edges[e] = make_int2((int)__ldg(p + e), (int)__ldg(p + E + e));
    }
}

// --- edge fetch helpers ----------------------------------------------------
__device__ __forceinline__ void fetch4(const void* ei, int E, int t,
                                       int* s, int* d) {
    if (g_ei64) {
        int4 ea = ((const int4*)g_edges)[t * 2];
        int4 eb = ((const int4*)g_edges)[t * 2 + 1];
        s[0] = ea.x; d[0] = ea.y; s[1] = ea.z; d[1] = ea.w;
        s[2] = eb.x; d[2] = eb.y; s[3] = eb.z; d[3] = eb.w;
    } else {
        const int* p = (const int*)ei;
        int4 ss = __ldg((const int4*)(p + t * 4));
        int4 dd = __ldg((const int4*)(p + E + t * 4));
        s[0] = ss.x; s[1] = ss.y; s[2] = ss.z; s[3] = ss.w;
        d[0] = dd.x; d[1] = dd.y; d[2] = dd.z; d[3] = dd.w;
    }
}

__device__ __forceinline__ void fetch1(const void* ei, int E, int e,
                                       int& s, int& d) {
    if (g_ei64) {
        int2 sd = g_edges[e];
        s = sd.x; d = sd.y;
    } else {
        const int* p = (const int*)ei;
        s = __ldg(p + e); d = __ldg(p + E + e);
    }
}

// --- node pass 1: dinv = rsqrt(deg+1), xs = x*dinv, a1 = xs ---------------
__global__ void k_l1(const float* __restrict__ x, int N) {
    int i = blockIdx.x * blockDim.x + threadIdx.x;
    if (i < N) {
        float4 xv = __ldg(&((const float4*)x)[i]);   // independent of k_deg
        pdl_wait();                                  // now deg is visible
        float di = rsqrtf((float)(g_deg[i] + 1));    // +1 = self loop
        g_dinv[i] = di;
        float4 v = make_float4(xv.x * di, xv.y * di, xv.z * di, xv.w * di);
        ((float4*)g_xs)[i] = v;
        ((float4*)g_a1)[i] = v;                      // self-loop contribution
    } else {
        pdl_wait();
    }
    pdl_trigger();
}

// --- layer-1 edge scatter: a1[dst] += xs[src] (4 edges/thread) ------------
__global__ void k_sc1(const void* ei, int E) {
    int t = blockIdx.x * blockDim.x + threadIdx.x;
    int e0 = t * 4;
    if (e0 + 3 < E) {
        int s[4], d[4];
        fetch4(ei, E, t, s, d);   // edges independent of k_l1
        pdl_wait();
        float4 v0 = __ldg(&((const float4*)g_xs)[s[0]]);
        float4 v1 = __ldg(&((const float4*)g_xs)[s[1]]);
        float4 v2 = __ldg(&((const float4*)g_xs)[s[2]]);
        float4 v3 = __ldg(&((const float4*)g_xs)[s[3]]);
        RED4(d[0], v0); RED4(d[1], v1); RED4(d[2], v2); RED4(d[3], v3);
    } else {
        pdl_wait();
        for (int e = e0; e < E; e++) {
            int s, d;
            fetch1(ei, E, e, s, d);
            float4 v = __ldg(&((const float4*)g_xs)[s]);
            RED4(d, v);
        }
    }
    pdl_trigger();
}

// --- node pass 2: h = relu(dinv*(a1@W1)+b1); h2 = (h@W2)*dinv; a2 = h2 ----
__global__ void k_l2(const float* __restrict__ W1, const float* __restrict__ b1,
                     const float* __restrict__ W2, int N) {
    __shared__ float sW1[64], sb1[16], sW2[32];
    int tid = threadIdx.x;
    if (tid < 64)              sW1[tid]      = W1[tid];
    else if (tid < 80)         sb1[tid - 64] = b1[tid - 64];
    else if (tid < 112)        sW2[tid - 80] = W2[tid - 80];
    __syncthreads();
    pdl_wait();

    int i = blockIdx.x * blockDim.x + tid;
    if (i < N) {
        float di = g_dinv[i];
        float4 av = ((const float4*)g_a1)[i];   // includes self loop
        float o0 = 0.f, o1 = 0.f;
#pragma unroll
        for (int k = 0; k < 16; k++) {
            float h = di * (av.x * sW1[k]      + av.y * sW1[16 + k] +
                            av.z * sW1[32 + k] + av.w * sW1[48 + k]) + sb1[k];
            h = fmaxf(h, 0.f);
            o0 += h * sW2[2 * k];
            o1 += h * sW2[2 * k + 1];
        }
        float2 v = make_float2(o0 * di, o1 * di);
        ((float2*)g_h2)[i] = v;
        ((float2*)g_a2)[i] = v;  // self-loop contribution
    }
    pdl_trigger();
}

// --- layer-2 edge scatter: a2[dst] += h2[src] (4 edges/thread) ------------
__global__ void k_sc2(const void* ei, int E) {
    int t = blockIdx.x * blockDim.x + threadIdx.x;
    int e0 = t * 4;
    if (e0 + 3 < E) {
        int s[4], d[4];
        fetch4(ei, E, t, s, d);   // edges independent of k_l2
        pdl_wait();
        float2 v0 = __ldg(&((const float2*)g_h2)[s[0]]);
        float2 v1 = __ldg(&((const float2*)g_h2)[s[1]]);
        float2 v2 = __ldg(&((const float2*)g_h2)[s[2]]);
        float2 v3 = __ldg(&((const float2*)g_h2)[s[3]]);
        RED2(d[0], v0); RED2(d[1], v1); RED2(d[2], v2); RED2(d[3], v3);
    } else {
        pdl_wait();
        for (int e = e0; e < E; e++) {
            int s, d;
            fetch1(ei, E, e, s, d);
            float2 v = __ldg(&((const float2*)g_h2)[s]);
            RED2(d, v);
        }
    }
    pdl_trigger();
}

// --- output: o = dinv*a2 + b2; log_softmax over 2 classes -----------------
__global__ void k_out(const float* __restrict__ b2, float* __restrict__ out, int N) {
    int i = blockIdx.x * blockDim.x + threadIdx.x;
    float2 bb = __ldg((const float2*)b2);   // independent
    pdl_wait();
    if (i >= N) return;
    float di = g_dinv[i];
    float2 a = ((const float2*)g_a2)[i];    // includes self loop
    float o0 = di * a.x + bb.x;
    float o1 = di * a.y + bb.y;
    float m = fmaxf(o0, o1);
    float ls = m + __logf(__expf(o0 - m) + __expf(o1 - m));
    ((float2*)out)[i] = make_float2(o0 - ls, o1 - ls);
}

extern "C" void kernel_launch(void* const* d_in, const int* in_sizes, int n_in,
                              void* d_out, int out_size) {
    const float* x  = (const float*)d_in[0];
    const void*  ei = d_in[1];
    int wi = 2;
    if (n_in >= 7 && in_sizes[2] < 16) wi = 3;  // skip num_nodes scalar
    const float* W1 = (const float*)d_in[wi];
    const float* b1 = (const float*)d_in[wi + 1];
    const float* W2 = (const float*)d_in[wi + 2];
    const float* b2 = (const float*)d_in[wi + 3];

    int N = in_sizes[0] / 4;
    int E = in_sizes[1] / 2;

    const int T = 256;
    unsigned gN  = (N + T - 1) / T;
    unsigned gE4 = ((E + 3) / 4 + T - 1) / T;

    void* degp = nullptr;
    cudaGetSymbolAddress(&degp, g_deg);

    cudaStream_t s1;
    cudaStreamCreateWithFlags(&s1, cudaStreamNonBlocking);
    cudaEvent_t evFork, evJoin;
    cudaEventCreateWithFlags(&evFork, cudaEventDisableTiming);
    cudaEventCreateWithFlags(&evJoin, cudaEventDisableTiming);

    k_detect<<<1, 32>>>((const unsigned*)ei);
    cudaEventRecord(evFork, 0);
    cudaStreamWaitEvent(s1, evFork, 0);

    // side stream: pack (int64 only; early-exit for int32)
    k_pack<<<gE4, T, 0, s1>>>(ei, E);
    cudaEventRecord(evJoin, s1);

    // main stream with PDL chain
    cudaMemsetAsync(degp, 0, (size_t)N * sizeof(int));
    k_deg<<<gE4, T>>>(ei, E);

    cudaLaunchAttribute pdlAttr[1];
    pdlAttr[0].id = cudaLaunchAttributeProgrammaticStreamSerialization;
    pdlAttr[0].val.programmaticStreamSerializationAllowed = 1;

    cudaLaunchConfig_t cfgN = {};
    cfgN.gridDim = dim3(gN); cfgN.blockDim = dim3(T);
    cfgN.stream = 0; cfgN.attrs = pdlAttr; cfgN.numAttrs = 1;

    cudaLaunchConfig_t cfgE = {};
    cfgE.gridDim = dim3(gE4); cfgE.blockDim = dim3(T);
    cfgE.stream = 0; cfgE.attrs = pdlAttr; cfgE.numAttrs = 1;

    cudaLaunchKernelEx(&cfgN, k_l1, x, N);

    cudaStreamWaitEvent(0, evJoin, 0);   // join pack before scatters
    cudaLaunchKernelEx(&cfgE, k_sc1, ei, E);
    cudaLaunchKernelEx(&cfgN, k_l2, W1, b1, W2, N);
    cudaLaunchKernelEx(&cfgE, k_sc2, ei, E);
    cudaLaunchKernelEx(&cfgN, k_out, b2, (float*)d_out, N);

    cudaEventDestroy(evFork);
    cudaEventDestroy(evJoin);
    cudaStreamDestroy(s1);
}